// round 1
// baseline (speedup 1.0000x reference)
#include <cuda_runtime.h>
#include <math.h>

#define BB 64
#define PP 8732
#define OO 32
#define CC 81
#define IMGF 224.0f
#define SEG 8
#define CHUNK ((PP + SEG - 1) / SEG)   // 1092

// ---------------- device scratch (no allocations allowed) ----------------
__device__ float              g_ov[BB * PP];
__device__ unsigned char      g_obj[BB * PP];
__device__ unsigned char      g_cls[BB * PP];
__device__ float              g_ce_neg[BB * PP];
__device__ unsigned long long g_pfo[BB * OO];
__device__ int                g_npos[BB];
__device__ float              g_acc[4];   // 0: sl1 sum, 1: pos ce sum, 2: hard-neg ce sum

// ---------------- init: zero accumulators each replay ----------------
__global__ void k_init() {
    int t = threadIdx.x;
    for (int i = t; i < BB * OO; i += blockDim.x) g_pfo[i] = 0ull;
    if (t < BB) g_npos[t] = 0;
    if (t < 4)  g_acc[t] = 0.0f;
}

// ---------------- kernel 1a: IoU matching ----------------
// grid: BB*SEG blocks, 256 threads. Per prior: max/argmax over 32 objects.
// Per object: running max over priors via packed u64 key (iou_bits<<32 | (~p)),
// so ties pick the LOWEST prior index (matches jnp.argmax first-max semantics).
__global__ void __launch_bounds__(256) k_match(const float* __restrict__ gt_boxes,
                                               const float* __restrict__ priors) {
    int b   = blockIdx.x / SEG;
    int seg = blockIdx.x % SEG;
    __shared__ float sx1[OO], sy1[OO], sx2[OO], sy2[OO], sar[OO];
    __shared__ unsigned long long spf[OO];
    int t = threadIdx.x;
    if (t < OO) {
        const float* g = gt_boxes + (b * OO + t) * 4;
        float x = g[0], y = g[1], w = g[2], h = g[3];
        float x1 = x / IMGF, y1 = y / IMGF;
        float x2 = (x + w) / IMGF, y2 = (y + h) / IMGF;
        sx1[t] = x1; sy1[t] = y1; sx2[t] = x2; sy2[t] = y2;
        sar[t] = (x2 - x1) * (y2 - y1);
        spf[t] = 0ull;
    }
    __syncthreads();

    unsigned long long pf[OO];
#pragma unroll
    for (int o = 0; o < OO; o++) pf[o] = 0ull;

    int p0 = seg * CHUNK;
    int p1 = p0 + CHUNK; if (p1 > PP) p1 = PP;

    for (int p = p0 + t; p < p1; p += 256) {
        float4 pr = ((const float4*)priors)[p];
        float px1 = pr.x - pr.z * 0.5f, py1 = pr.y - pr.w * 0.5f;
        float px2 = pr.x + pr.z * 0.5f, py2 = pr.y + pr.w * 0.5f;
        float pa  = (px2 - px1) * (py2 - py1);
        float best = -1.0f;
        int   obj  = 0;
        unsigned int rp = 0xFFFFFFFFu - (unsigned int)p;
#pragma unroll
        for (int o = 0; o < OO; o++) {
            float lx = fmaxf(sx1[o], px1), ly = fmaxf(sy1[o], py1);
            float rx = fminf(sx2[o], px2), ry = fminf(sy2[o], py2);
            float w_ = fmaxf(rx - lx, 0.0f), h_ = fmaxf(ry - ly, 0.0f);
            float inter = w_ * h_;
            float iou = inter / (sar[o] + pa - inter);   // IEEE div, matches XLA
            if (iou > best) { best = iou; obj = o; }     // strict > : first max wins
            unsigned long long key =
                ((unsigned long long)__float_as_uint(iou) << 32) | (unsigned long long)rp;
            if (key > pf[o]) pf[o] = key;
        }
        g_ov[b * PP + p]  = best;
        g_obj[b * PP + p] = (unsigned char)obj;
    }
#pragma unroll
    for (int o = 0; o < OO; o++) atomicMax(&spf[o], pf[o]);
    __syncthreads();
    if (t < OO) atomicMax(&g_pfo[b * OO + t], spf[t]);
}

// ---------------- kernel 1b: forced assignment, labels, loc loss ----------------
__global__ void __launch_bounds__(256) k_assign(const float* __restrict__ gt_boxes,
                                                const int*   __restrict__ gt_labels,
                                                const float* __restrict__ priors,
                                                const float* __restrict__ pred_locs) {
    int b   = blockIdx.x / SEG;
    int seg = blockIdx.x % SEG;
    __shared__ int   spfo[OO];
    __shared__ float scx[OO], scy[OO], scw[OO], sch[OO];
    __shared__ int   slab[OO];
    __shared__ float swarp[8];
    __shared__ int   siwarp[8];
    int t = threadIdx.x;
    if (t < OO) {
        unsigned long long k = g_pfo[b * OO + t];
        spfo[t] = (int)(0xFFFFFFFFu - (unsigned int)(k & 0xFFFFFFFFull));
        const float* g = gt_boxes + (b * OO + t) * 4;
        float x = g[0], y = g[1], w = g[2], h = g[3];
        float x1 = x / IMGF, y1 = y / IMGF;
        float x2 = (x + w) / IMGF, y2 = (y + h) / IMGF;
        scx[t] = (x1 + x2) * 0.5f;
        scy[t] = (y1 + y2) * 0.5f;
        scw[t] = x2 - x1;
        sch[t] = y2 - y1;
        slab[t] = gt_labels[b * OO + t];
    }
    __syncthreads();

    int p0 = seg * CHUNK;
    int p1 = p0 + CHUNK; if (p1 > PP) p1 = PP;
    int   npos = 0;
    float sl1  = 0.0f;

    for (int p = p0 + t; p < p1; p += 256) {
        int bp = b * PP + p;
        float ov = g_ov[bp];
        int obj  = g_obj[bp];
        // forced match: sequential .at[].set with last-write-wins over o
#pragma unroll
        for (int o = 0; o < OO; o++)
            if (spfo[o] == p) { obj = o; ov = 1.0f; }
        int lab = slab[obj];
        if (ov < 0.5f) lab = 0;
        g_cls[bp] = (unsigned char)lab;
        if (lab != 0) {
            npos++;
            float4 pr = ((const float4*)priors)[p];
            float gx = (scx[obj] - pr.x) / (pr.z / 10.0f);
            float gy = (scy[obj] - pr.y) / (pr.w / 10.0f);
            float gw = logf(scw[obj] / pr.z) * 5.0f;
            float gh = logf(sch[obj] / pr.w) * 5.0f;
            float4 pl = ((const float4*)pred_locs)[bp];
            float d, s = 0.0f;
            d = fabsf(pl.x - gx); s += (d < 1.0f) ? 0.5f * d * d : d - 0.5f;
            d = fabsf(pl.y - gy); s += (d < 1.0f) ? 0.5f * d * d : d - 0.5f;
            d = fabsf(pl.z - gw); s += (d < 1.0f) ? 0.5f * d * d : d - 0.5f;
            d = fabsf(pl.w - gh); s += (d < 1.0f) ? 0.5f * d * d : d - 0.5f;
            sl1 += s;
        }
    }
#pragma unroll
    for (int off = 16; off; off >>= 1) {
        sl1  += __shfl_xor_sync(0xffffffffu, sl1,  off);
        npos += __shfl_xor_sync(0xffffffffu, npos, off);
    }
    if ((t & 31) == 0) { swarp[t >> 5] = sl1; siwarp[t >> 5] = npos; }
    __syncthreads();
    if (t == 0) {
        float S = 0.0f; int N = 0;
        for (int i = 0; i < 8; i++) { S += swarp[i]; N += siwarp[i]; }
        if (S != 0.0f) atomicAdd(&g_acc[0], S);
        if (N)         atomicAdd(&g_npos[b], N);
    }
}

// ---------------- kernel 2: per-prior cross entropy (warp per prior) ----------------
__global__ void __launch_bounds__(256) k_ce(const float* __restrict__ scores) {
    int warp = (int)((blockIdx.x * blockDim.x + threadIdx.x) >> 5);
    int lane = threadIdx.x & 31;
    if (warp >= BB * PP) return;
    const float* row = scores + (size_t)warp * CC;
    float x0 = row[lane];
    float x1 = row[lane + 32];
    float x2 = (lane < CC - 64) ? row[lane + 64] : -3.402823466e38f;
    float m = fmaxf(fmaxf(x0, x1), x2);
#pragma unroll
    for (int off = 16; off; off >>= 1) m = fmaxf(m, __shfl_xor_sync(0xffffffffu, m, off));
    float s = __expf(x0 - m) + __expf(x1 - m);
    if (lane < CC - 64) s += __expf(x2 - m);
#pragma unroll
    for (int off = 16; off; off >>= 1) s += __shfl_xor_sync(0xffffffffu, s, off);
    int cls = g_cls[warp];
    float v = (cls < 32) ? x0 : ((cls < 64) ? x1 : x2);
    float sc = __shfl_sync(0xffffffffu, v, cls & 31);
    float ce = m + __logf(s) - sc;
    if (lane == 0) {
        if (cls != 0) {
            g_ce_neg[warp] = 0.0f;
            atomicAdd(&g_acc[1], ce);   // positives are rare -> few atomics
        } else {
            g_ce_neg[warp] = ce;
        }
    }
}

// ---------------- kernel 3: per-image radix-select top-k sum ----------------
// CE >= 0 so float bits compare like values. 4 byte passes find the k-th
// largest value t exactly; topk_sum = sum(v > t) + K_rem * t (exact under ties).
__global__ void __launch_bounds__(256) k_topk() {
    int b = blockIdx.x;
    const float* row = g_ce_neg + b * PP;
    __shared__ int hist[256];
    __shared__ unsigned int s_prefix;
    __shared__ int s_K;
    __shared__ float swarp[8];
    int t = threadIdx.x;
    int np = g_npos[b];
    int k = 3 * ((np > 1) ? np : 1);
    if (k > PP) k = PP;
    if (t == 0) { s_prefix = 0u; s_K = k; }

    for (int byte = 3; byte >= 0; --byte) {
        hist[t] = 0;
        __syncthreads();
        unsigned int pref = s_prefix;
        for (int i = t; i < PP; i += 256) {
            unsigned int u = __float_as_uint(row[i]);
            bool ok = (byte == 3) || ((u >> ((byte + 1) * 8)) == pref);
            if (ok) atomicAdd(&hist[(u >> (byte * 8)) & 255], 1);
        }
        __syncthreads();
        if (t == 0) {
            int K = s_K, cum = 0, sel = 0;
            for (int bin = 255; bin >= 0; --bin) {
                cum += hist[bin];
                if (cum >= K) { sel = bin; K -= (cum - hist[bin]); break; }
            }
            s_prefix = (s_prefix << 8) | (unsigned int)sel;
            s_K = K;
        }
        __syncthreads();
    }
    unsigned int tb = s_prefix;
    float tv = __uint_as_float(tb);
    float sum = 0.0f;
    for (int i = t; i < PP; i += 256) {
        float v = row[i];
        if (__float_as_uint(v) > tb) sum += v;
    }
#pragma unroll
    for (int off = 16; off; off >>= 1) sum += __shfl_xor_sync(0xffffffffu, sum, off);
    if ((t & 31) == 0) swarp[t >> 5] = sum;
    __syncthreads();
    if (t == 0) {
        float S = 0.0f;
        for (int i = 0; i < 8; i++) S += swarp[i];
        S += (float)s_K * tv;
        atomicAdd(&g_acc[2], S);
    }
}

// ---------------- kernel 4: final combine ----------------
__global__ void k_final(float* out) {
    int t = threadIdx.x;  // 32 threads
    int n1 = g_npos[t], n2 = g_npos[t + 32];
    int tp = n1 + n2;
    float ncl = (float)((n1 > 1) ? n1 : 1) + (float)((n2 > 1) ? n2 : 1);
#pragma unroll
    for (int off = 16; off; off >>= 1) {
        tp  += __shfl_xor_sync(0xffffffffu, tp,  off);
        ncl += __shfl_xor_sync(0xffffffffu, ncl, off);
    }
    if (t == 0) {
        float loc = 0.0f;
        if (tp > 0) {
            int den = tp * 4; if (den < 1) den = 1;
            loc = g_acc[0] / (float)den;
        }
        float conf = (g_acc[1] + g_acc[2]) / ncl;
        out[0] = conf + loc;
    }
}

// ---------------- launch ----------------
extern "C" void kernel_launch(void* const* d_in, const int* in_sizes, int n_in,
                              void* d_out, int out_size) {
    const float* pred_locs   = (const float*)d_in[0];
    const float* pred_scores = (const float*)d_in[1];
    const float* gt_boxes    = (const float*)d_in[2];
    const int*   gt_labels   = (const int*)d_in[3];
    const float* priors      = (const float*)d_in[4];
    float* out = (float*)d_out;

    k_init<<<1, 256>>>();
    k_match<<<BB * SEG, 256>>>(gt_boxes, priors);
    k_assign<<<BB * SEG, 256>>>(gt_boxes, gt_labels, priors, pred_locs);
    k_ce<<<(BB * PP + 7) / 8, 256>>>(pred_scores);
    k_topk<<<BB, 256>>>();
    k_final<<<1, 32>>>(out);
}